// round 16
// baseline (speedup 1.0000x reference)
#include <cuda_runtime.h>
#include <cstdint>
#include <math.h>

#define T_TOK 4096
#define HDIM  2048
#define NEXP  16
#define TOPK  4
#define FE    1408
#define FS    5632

// Scratch: max(T*K*FE, T*FS) floats -- both exactly 23,068,672 (92.3 MB)
__device__ float g_hdn[23068672];
__device__ int   g_selE[T_TOK * TOPK];
__device__ float g_selW[T_TOK * TOPK];
__device__ int   g_rowtok[T_TOK * TOPK];
__device__ float g_roww[T_TOK * TOPK];
__device__ float g_sgate[T_TOK];
__device__ int   g_cnt[NEXP];
__device__ int   g_off[NEXP + 1];
__device__ int   g_cur[NEXP];

// ---------------------------------------------------------------------------
// Router: one warp per token (proven)
// ---------------------------------------------------------------------------
__global__ void k_router(const float* __restrict__ X,
                         const float* __restrict__ GW,
                         const float* __restrict__ SEGW) {
    int warp = (blockIdx.x * blockDim.x + threadIdx.x) >> 5;
    int lane = threadIdx.x & 31;
    if (warp >= T_TOK) return;
    const float* xr = X + (size_t)warp * HDIM;

    float part[NEXP];
    float ps = 0.f;
#pragma unroll
    for (int e = 0; e < NEXP; e++) part[e] = 0.f;

    for (int h = lane; h < HDIM; h += 32) {
        float xv = xr[h];
#pragma unroll
        for (int e = 0; e < NEXP; e++) part[e] += xv * GW[e * HDIM + h];
        ps += xv * SEGW[h];
    }
#pragma unroll
    for (int e = 0; e < NEXP; e++) {
#pragma unroll
        for (int o = 16; o > 0; o >>= 1)
            part[e] += __shfl_down_sync(0xffffffffu, part[e], o);
    }
#pragma unroll
    for (int o = 16; o > 0; o >>= 1)
        ps += __shfl_down_sync(0xffffffffu, ps, o);

    if (lane == 0) {
        float m = part[0];
#pragma unroll
        for (int e = 1; e < NEXP; e++) m = fmaxf(m, part[e]);
        float r[NEXP];
        float den = 0.f;
#pragma unroll
        for (int e = 0; e < NEXP; e++) { r[e] = expf(part[e] - m); den += r[e]; }
        float inv = 1.f / den;
#pragma unroll
        for (int e = 0; e < NEXP; e++) r[e] *= inv;

        int   se[TOPK];
        float sw[TOPK];
        float s4 = 0.f;
#pragma unroll
        for (int k = 0; k < TOPK; k++) {
            int bi = 0; float bv = -1.f;
#pragma unroll
            for (int e = 0; e < NEXP; e++)
                if (r[e] > bv) { bv = r[e]; bi = e; }
            se[k] = bi; sw[k] = bv; s4 += bv;
            r[bi] = -2.f;
        }
        float invs4 = 1.f / s4;
#pragma unroll
        for (int k = 0; k < TOPK; k++) {
            g_selE[warp * TOPK + k] = se[k];
            g_selW[warp * TOPK + k] = sw[k] * invs4;
        }
        g_sgate[warp] = 1.f / (1.f + expf(-ps));
    }
}

// ---------------------------------------------------------------------------
// offsets: single block; histogram selE in smem, prefix-sum, reset cursors
// ---------------------------------------------------------------------------
__global__ void k_offsets() {
    __shared__ int scnt[NEXP];
    int tid = threadIdx.x;
    if (tid < NEXP) scnt[tid] = 0;
    __syncthreads();
    for (int i = tid; i < T_TOK * TOPK; i += blockDim.x)
        atomicAdd(&scnt[g_selE[i]], 1);
    __syncthreads();
    if (tid == 0) {
        int acc = 0;
        for (int e = 0; e < NEXP; e++) {
            g_cnt[e] = scnt[e];
            g_off[e] = acc;
            acc += scnt[e];
            g_cur[e] = 0;
        }
        g_off[NEXP] = acc;
    }
}

// ---------------------------------------------------------------------------
__global__ void k_assign() {
    int t = blockIdx.x * blockDim.x + threadIdx.x;
    if (t >= T_TOK) return;
#pragma unroll
    for (int k = 0; k < TOPK; k++) {
        int e = g_selE[t * TOPK + k];
        int slot = atomicAdd(&g_cur[e], 1);
        int pos = g_off[e] + slot;
        g_rowtok[pos] = t;
        g_roww[pos] = g_selW[t * TOPK + k];
    }
}

// ---------------------------------------------------------------------------
// Packed fp32x2 helpers (proven R11-R15)
// ---------------------------------------------------------------------------
__device__ __forceinline__ unsigned long long pk2(float x) {
    unsigned long long r;
    asm("mov.b64 %0, {%1, %1};" : "=l"(r) : "f"(x));
    return r;
}
__device__ __forceinline__ void fma2(unsigned long long& d,
                                     unsigned long long a,
                                     unsigned long long b) {
    asm("fma.rn.f32x2 %0, %1, %2, %0;" : "+l"(d) : "l"(a), "l"(b));
}
__device__ __forceinline__ float2 up2(unsigned long long v) {
    float lo, hi;
    asm("mov.b64 {%0, %1}, %2;" : "=f"(lo), "=f"(hi) : "l"(v));
    return make_float2(lo, hi);
}

// ---------------------------------------------------------------------------
// Fused gate+up GEMM (R15 core; launch_bounds 128,3 -> reg cap 168,
// 3 CTAs/SM = 3 warps/SMSP for latency hiding; profile showed fma=74.8%
// at 2 warps/SMSP, 248 regs)
// ---------------------------------------------------------------------------
template <int GATHER>
__global__ void __launch_bounds__(128, 3)
k_gateup(const float* __restrict__ X,
         const float* __restrict__ Wgb,
         const float* __restrict__ Wub,
         int N, int Kd) {
    int rows, base;
    const float* Wg;
    const float* Wu;
    if (GATHER) {
        int e = blockIdx.z;
        rows = g_cnt[e];
        base = g_off[e];
        size_t wo = (size_t)e * N * Kd;
        Wg = Wgb + wo; Wu = Wub + wo;
    } else {
        rows = T_TOK; base = 0; Wg = Wgb; Wu = Wub;
    }
    int rowBase = blockIdx.y * 128;
    if (rowBase >= rows) return;
    int colBase = blockIdx.x * 64;

    __shared__ float As[2][16][132];
    __shared__ float Bs[2][16][132];

    const int tid = threadIdx.x;
    const int tx = tid & 15;
    const int ty = tid >> 4;

    int ar[4], ac[4];
    const float* aptr[4];
    bool aval[4];
    const float* bptr[4];
    int br[4], bc[4];
#pragma unroll
    for (int i = 0; i < 4; i++) {
        int idx = tid + i * 128;
        ar[i] = idx >> 2;
        ac[i] = (idx & 3) * 4;
        int grow = rowBase + ar[i];
        aval[i] = grow < rows;
        if (GATHER) {
            int tok = aval[i] ? g_rowtok[base + grow] : 0;
            aptr[i] = X + (size_t)tok * Kd + ac[i];
        } else {
            aptr[i] = X + (size_t)(aval[i] ? grow : 0) * Kd + ac[i];
        }
        br[i] = idx >> 2;
        bc[i] = (idx & 3) * 4;
        if (br[i] < 64)
            bptr[i] = Wg + (size_t)(colBase + br[i]) * Kd + bc[i];
        else
            bptr[i] = Wu + (size_t)(colBase + br[i] - 64) * Kd + bc[i];
    }

    unsigned long long accg2[8][4];
    unsigned long long accu2[8][4];
#pragma unroll
    for (int p = 0; p < 8; p++)
#pragma unroll
        for (int j = 0; j < 4; j++) { accg2[p][j] = 0ULL; accu2[p][j] = 0ULL; }

    const int KT = Kd >> 4;

    float4 sva[4], svb[4];
#pragma unroll
    for (int i = 0; i < 4; i++) {
        sva[i] = aval[i] ? *reinterpret_cast<const float4*>(aptr[i])
                         : make_float4(0.f, 0.f, 0.f, 0.f);
        svb[i] = *reinterpret_cast<const float4*>(bptr[i]);
    }
#pragma unroll
    for (int i = 0; i < 4; i++) {
        As[0][ac[i] + 0][ar[i]] = sva[i].x;
        As[0][ac[i] + 1][ar[i]] = sva[i].y;
        As[0][ac[i] + 2][ar[i]] = sva[i].z;
        As[0][ac[i] + 3][ar[i]] = sva[i].w;
        Bs[0][bc[i] + 0][br[i]] = svb[i].x;
        Bs[0][bc[i] + 1][br[i]] = svb[i].y;
        Bs[0][bc[i] + 2][br[i]] = svb[i].z;
        Bs[0][bc[i] + 3][br[i]] = svb[i].w;
    }
    __syncthreads();

    for (int kt = 0; kt < KT; kt++) {
        int cur = kt & 1;
        if (kt + 1 < KT) {
            int k0 = (kt + 1) << 4;
#pragma unroll
            for (int i = 0; i < 4; i++) {
                sva[i] = aval[i] ? *reinterpret_cast<const float4*>(aptr[i] + k0)
                                 : make_float4(0.f, 0.f, 0.f, 0.f);
                svb[i] = *reinterpret_cast<const float4*>(bptr[i] + k0);
            }
        }
#pragma unroll
        for (int kk = 0; kk < 16; kk++) {
            const ulonglong2* ap =
                reinterpret_cast<const ulonglong2*>(&As[cur][kk][ty * 16]);
            ulonglong2 av0 = ap[0], av1 = ap[1], av2 = ap[2], av3 = ap[3];
            unsigned long long a2[8] = {av0.x, av0.y, av1.x, av1.y,
                                        av2.x, av2.y, av3.x, av3.y};
            float4 bg = *reinterpret_cast<const float4*>(&Bs[cur][kk][tx * 4]);
            float4 bu = *reinterpret_cast<const float4*>(&Bs[cur][kk][64 + tx * 4]);
            unsigned long long bg2[4] = {pk2(bg.x), pk2(bg.y), pk2(bg.z), pk2(bg.w)};
            unsigned long long bu2[4] = {pk2(bu.x), pk2(bu.y), pk2(bu.z), pk2(bu.w)};
#pragma unroll
            for (int p = 0; p < 8; p++) {
#pragma unroll
                for (int j = 0; j < 4; j++) {
                    fma2(accg2[p][j], a2[p], bg2[j]);
                    fma2(accu2[p][j], a2[p], bu2[j]);
                }
            }
        }
        if (kt + 1 < KT) {
            int nxt = cur ^ 1;
#pragma unroll
            for (int i = 0; i < 4; i++) {
                As[nxt][ac[i] + 0][ar[i]] = sva[i].x;
                As[nxt][ac[i] + 1][ar[i]] = sva[i].y;
                As[nxt][ac[i] + 2][ar[i]] = sva[i].z;
                As[nxt][ac[i] + 3][ar[i]] = sva[i].w;
                Bs[nxt][bc[i] + 0][br[i]] = svb[i].x;
                Bs[nxt][bc[i] + 1][br[i]] = svb[i].y;
                Bs[nxt][bc[i] + 2][br[i]] = svb[i].z;
                Bs[nxt][bc[i] + 3][br[i]] = svb[i].w;
            }
        }
        __syncthreads();
    }

#pragma unroll
    for (int p = 0; p < 8; p++) {
        float2 g2[4], u2[4];
#pragma unroll
        for (int j = 0; j < 4; j++) { g2[j] = up2(accg2[p][j]); u2[j] = up2(accu2[p][j]); }
        int growL = rowBase + ty * 16 + 2 * p;
        if (growL < rows) {
            float4 hv;
            hv.x = (g2[0].x / (1.f + expf(-g2[0].x))) * u2[0].x;
            hv.y = (g2[1].x / (1.f + expf(-g2[1].x))) * u2[1].x;
            hv.z = (g2[2].x / (1.f + expf(-g2[2].x))) * u2[2].x;
            hv.w = (g2[3].x / (1.f + expf(-g2[3].x))) * u2[3].x;
            *reinterpret_cast<float4*>(
                &g_hdn[(size_t)(base + growL) * N + colBase + tx * 4]) = hv;
        }
        int growH = growL + 1;
        if (growH < rows) {
            float4 hv;
            hv.x = (g2[0].y / (1.f + expf(-g2[0].y))) * u2[0].y;
            hv.y = (g2[1].y / (1.f + expf(-g2[1].y))) * u2[1].y;
            hv.z = (g2[2].y / (1.f + expf(-g2[2].y))) * u2[2].y;
            hv.w = (g2[3].y / (1.f + expf(-g2[3].y))) * u2[3].y;
            *reinterpret_cast<float4*>(
                &g_hdn[(size_t)(base + growH) * N + colBase + tx * 4]) = hv;
        }
    }
}

// ---------------------------------------------------------------------------
// Down GEMM (R15 core; launch_bounds 128,3)
// ---------------------------------------------------------------------------
template <int GATHER>
__global__ void __launch_bounds__(128, 3)
k_down(const float* __restrict__ Wdb,
       float* __restrict__ Out,
       int N, int Kd) {
    int rows, base;
    const float* Wd;
    if (GATHER) {
        int e = blockIdx.z;
        rows = g_cnt[e];
        base = g_off[e];
        Wd = Wdb + (size_t)e * N * Kd;
    } else {
        rows = T_TOK; base = 0; Wd = Wdb;
    }
    int rowBase = blockIdx.y * 128;
    if (rowBase >= rows) return;
    int colBase = blockIdx.x * 128;

    __shared__ float As[2][16][132];
    __shared__ float Bs[2][16][132];

    const int tid = threadIdx.x;
    const int tx = tid & 15;
    const int ty = tid >> 4;

    int ar[4], ac[4];
    const float* aptr[4];
    bool aval[4];
    const float* bptr[4];
    int br[4], bc[4];
#pragma unroll
    for (int i = 0; i < 4; i++) {
        int idx = tid + i * 128;
        ar[i] = idx >> 2;
        ac[i] = (idx & 3) * 4;
        int grow = rowBase + ar[i];
        aval[i] = grow < rows;
        aptr[i] = g_hdn + (size_t)(base + (aval[i] ? grow : 0)) * Kd + ac[i];
        br[i] = idx >> 2;
        bc[i] = (idx & 3) * 4;
        bptr[i] = Wd + (size_t)(colBase + br[i]) * Kd + bc[i];
    }

    unsigned long long acc2[8][8];
#pragma unroll
    for (int p = 0; p < 8; p++)
#pragma unroll
        for (int j = 0; j < 8; j++) acc2[p][j] = 0ULL;

    const int KT = Kd >> 4;

    float4 sva[4], svb[4];
#pragma unroll
    for (int i = 0; i < 4; i++) {
        sva[i] = aval[i] ? *reinterpret_cast<const float4*>(aptr[i])
                         : make_float4(0.f, 0.f, 0.f, 0.f);
        svb[i] = *reinterpret_cast<const float4*>(bptr[i]);
    }
#pragma unroll
    for (int i = 0; i < 4; i++) {
        As[0][ac[i] + 0][ar[i]] = sva[i].x;
        As[0][ac[i] + 1][ar[i]] = sva[i].y;
        As[0][ac[i] + 2][ar[i]] = sva[i].z;
        As[0][ac[i] + 3][ar[i]] = sva[i].w;
        Bs[0][bc[i] + 0][br[i]] = svb[i].x;
        Bs[0][bc[i] + 1][br[i]] = svb[i].y;
        Bs[0][bc[i] + 2][br[i]] = svb[i].z;
        Bs[0][bc[i] + 3][br[i]] = svb[i].w;
    }
    __syncthreads();

    for (int kt = 0; kt < KT; kt++) {
        int cur = kt & 1;
        if (kt + 1 < KT) {
            int k0 = (kt + 1) << 4;
#pragma unroll
            for (int i = 0; i < 4; i++) {
                sva[i] = aval[i] ? *reinterpret_cast<const float4*>(aptr[i] + k0)
                                 : make_float4(0.f, 0.f, 0.f, 0.f);
                svb[i] = *reinterpret_cast<const float4*>(bptr[i] + k0);
            }
        }
#pragma unroll
        for (int kk = 0; kk < 16; kk++) {
            const ulonglong2* ap =
                reinterpret_cast<const ulonglong2*>(&As[cur][kk][ty * 16]);
            ulonglong2 av0 = ap[0], av1 = ap[1], av2 = ap[2], av3 = ap[3];
            unsigned long long a2[8] = {av0.x, av0.y, av1.x, av1.y,
                                        av2.x, av2.y, av3.x, av3.y};
            float4 b0 = *reinterpret_cast<const float4*>(&Bs[cur][kk][tx * 4]);
            float4 b1 = *reinterpret_cast<const float4*>(&Bs[cur][kk][64 + tx * 4]);
            unsigned long long b2[8] = {pk2(b0.x), pk2(b0.y), pk2(b0.z), pk2(b0.w),
                                        pk2(b1.x), pk2(b1.y), pk2(b1.z), pk2(b1.w)};
#pragma unroll
            for (int p = 0; p < 8; p++)
#pragma unroll
                for (int j = 0; j < 8; j++)
                    fma2(acc2[p][j], a2[p], b2[j]);
        }
        if (kt + 1 < KT) {
            int nxt = cur ^ 1;
#pragma unroll
            for (int i = 0; i < 4; i++) {
                As[nxt][ac[i] + 0][ar[i]] = sva[i].x;
                As[nxt][ac[i] + 1][ar[i]] = sva[i].y;
                As[nxt][ac[i] + 2][ar[i]] = sva[i].z;
                As[nxt][ac[i] + 3][ar[i]] = sva[i].w;
                Bs[nxt][bc[i] + 0][br[i]] = svb[i].x;
                Bs[nxt][bc[i] + 1][br[i]] = svb[i].y;
                Bs[nxt][bc[i] + 2][br[i]] = svb[i].z;
                Bs[nxt][bc[i] + 3][br[i]] = svb[i].w;
            }
        }
        __syncthreads();
    }

#pragma unroll
    for (int p = 0; p < 8; p++) {
        float2 c2[8];
#pragma unroll
        for (int j = 0; j < 8; j++) c2[j] = up2(acc2[p][j]);
#pragma unroll
        for (int half = 0; half < 2; half++) {
            int grow = rowBase + ty * 16 + 2 * p + half;
            if (grow >= rows) continue;
            if (GATHER) {
                int tok = g_rowtok[base + grow];
                float w = g_roww[base + grow];
                float* op0 = Out + (size_t)tok * N + colBase + tx * 4;
                float* op1 = op0 + 64;
#pragma unroll
                for (int j = 0; j < 4; j++) {
                    float v0 = half ? c2[j].y : c2[j].x;
                    float v1 = half ? c2[j + 4].y : c2[j + 4].x;
                    atomicAdd(op0 + j, w * v0);
                    atomicAdd(op1 + j, w * v1);
                }
            } else {
                float w = g_sgate[grow];
                float* op0 = Out + (size_t)grow * N + colBase + tx * 4;
                float4 s0, s1;
                s0.x = w * (half ? c2[0].y : c2[0].x);
                s0.y = w * (half ? c2[1].y : c2[1].x);
                s0.z = w * (half ? c2[2].y : c2[2].x);
                s0.w = w * (half ? c2[3].y : c2[3].x);
                s1.x = w * (half ? c2[4].y : c2[4].x);
                s1.y = w * (half ? c2[5].y : c2[5].x);
                s1.z = w * (half ? c2[6].y : c2[6].x);
                s1.w = w * (half ? c2[7].y : c2[7].x);
                *reinterpret_cast<float4*>(op0) = s0;
                *reinterpret_cast<float4*>(op0 + 64) = s1;
            }
        }
    }
}

// ---------------------------------------------------------------------------
extern "C" void kernel_launch(void* const* d_in, const int* in_sizes, int n_in,
                              void* d_out, int out_size) {
    const float* x    = (const float*)d_in[0];  // [B,S,H]
    const float* gw   = (const float*)d_in[1];  // [E,H]
    const float* egw  = (const float*)d_in[2];  // [E,FE,H]
    const float* euw  = (const float*)d_in[3];  // [E,FE,H]
    const float* edw  = (const float*)d_in[4];  // [E,H,FE]
    const float* sgw  = (const float*)d_in[5];  // [FS,H]
    const float* suw  = (const float*)d_in[6];  // [FS,H]
    const float* sdw  = (const float*)d_in[7];  // [H,FS]
    const float* segw = (const float*)d_in[8];  // [1,H]
    float* out = (float*)d_out;

    k_router<<<T_TOK / 8, 256>>>(x, gw, segw);       // 1
    k_offsets<<<1, 256>>>();                          // 2
    k_assign<<<T_TOK / 256, 256>>>();                 // 3

    // 4th launch = profiled GEMM. Shared path first; its down kernel
    // initializes out with plain weighted stores (no memset).
    k_gateup<0><<<dim3(FS / 64, T_TOK / 128, 1), 128>>>(x, sgw, suw, FS, HDIM);
    k_down<0><<<dim3(HDIM / 128, T_TOK / 128, 1), 128>>>(sdw, out, HDIM, FS);

    // Expert path: fused gate+up (gathered), then down + weighted atomic add
    k_gateup<1><<<dim3(FE / 64, T_TOK / 128, NEXP), 128>>>(x, egw, euw, FE, HDIM);
    k_down<1><<<dim3(HDIM / 128, T_TOK / 128, NEXP), 128>>>(edw, out, HDIM, FE);
}

// round 17
// speedup vs baseline: 1.3824x; 1.3824x over previous
#include <cuda_runtime.h>
#include <cstdint>
#include <math.h>

#define T_TOK 4096
#define HDIM  2048
#define NEXP  16
#define TOPK  4
#define FE    1408
#define FS    5632

// Scratch: max(T*K*FE, T*FS) floats -- both exactly 23,068,672 (92.3 MB)
__device__ float g_hdn[23068672];
__device__ int   g_selE[T_TOK * TOPK];
__device__ float g_selW[T_TOK * TOPK];
__device__ int   g_rowtok[T_TOK * TOPK];
__device__ float g_roww[T_TOK * TOPK];
__device__ float g_sgate[T_TOK];
__device__ int   g_cnt[NEXP];
__device__ int   g_off[NEXP + 1];
__device__ int   g_cur[NEXP];

// ---------------------------------------------------------------------------
// Router: one warp per token (proven)
// ---------------------------------------------------------------------------
__global__ void k_router(const float* __restrict__ X,
                         const float* __restrict__ GW,
                         const float* __restrict__ SEGW) {
    int warp = (blockIdx.x * blockDim.x + threadIdx.x) >> 5;
    int lane = threadIdx.x & 31;
    if (warp >= T_TOK) return;
    const float* xr = X + (size_t)warp * HDIM;

    float part[NEXP];
    float ps = 0.f;
#pragma unroll
    for (int e = 0; e < NEXP; e++) part[e] = 0.f;

    for (int h = lane; h < HDIM; h += 32) {
        float xv = xr[h];
#pragma unroll
        for (int e = 0; e < NEXP; e++) part[e] += xv * GW[e * HDIM + h];
        ps += xv * SEGW[h];
    }
#pragma unroll
    for (int e = 0; e < NEXP; e++) {
#pragma unroll
        for (int o = 16; o > 0; o >>= 1)
            part[e] += __shfl_down_sync(0xffffffffu, part[e], o);
    }
#pragma unroll
    for (int o = 16; o > 0; o >>= 1)
        ps += __shfl_down_sync(0xffffffffu, ps, o);

    if (lane == 0) {
        float m = part[0];
#pragma unroll
        for (int e = 1; e < NEXP; e++) m = fmaxf(m, part[e]);
        float r[NEXP];
        float den = 0.f;
#pragma unroll
        for (int e = 0; e < NEXP; e++) { r[e] = expf(part[e] - m); den += r[e]; }
        float inv = 1.f / den;
#pragma unroll
        for (int e = 0; e < NEXP; e++) r[e] *= inv;

        int   se[TOPK];
        float sw[TOPK];
        float s4 = 0.f;
#pragma unroll
        for (int k = 0; k < TOPK; k++) {
            int bi = 0; float bv = -1.f;
#pragma unroll
            for (int e = 0; e < NEXP; e++)
                if (r[e] > bv) { bv = r[e]; bi = e; }
            se[k] = bi; sw[k] = bv; s4 += bv;
            r[bi] = -2.f;
        }
        float invs4 = 1.f / s4;
#pragma unroll
        for (int k = 0; k < TOPK; k++) {
            g_selE[warp * TOPK + k] = se[k];
            g_selW[warp * TOPK + k] = sw[k] * invs4;
        }
        g_sgate[warp] = 1.f / (1.f + expf(-ps));
    }
}

// ---------------------------------------------------------------------------
__global__ void k_offsets() {
    __shared__ int scnt[NEXP];
    int tid = threadIdx.x;
    if (tid < NEXP) scnt[tid] = 0;
    __syncthreads();
    for (int i = tid; i < T_TOK * TOPK; i += blockDim.x)
        atomicAdd(&scnt[g_selE[i]], 1);
    __syncthreads();
    if (tid == 0) {
        int acc = 0;
        for (int e = 0; e < NEXP; e++) {
            g_cnt[e] = scnt[e];
            g_off[e] = acc;
            acc += scnt[e];
            g_cur[e] = 0;
        }
        g_off[NEXP] = acc;
    }
}

// ---------------------------------------------------------------------------
__global__ void k_assign() {
    int t = blockIdx.x * blockDim.x + threadIdx.x;
    if (t >= T_TOK) return;
#pragma unroll
    for (int k = 0; k < TOPK; k++) {
        int e = g_selE[t * TOPK + k];
        int slot = atomicAdd(&g_cur[e], 1);
        int pos = g_off[e] + slot;
        g_rowtok[pos] = t;
        g_roww[pos] = g_selW[t * TOPK + k];
    }
}

// ---------------------------------------------------------------------------
// Packed fp32x2 + cp.async helpers
// ---------------------------------------------------------------------------
__device__ __forceinline__ unsigned long long pk2(float x) {
    unsigned long long r;
    asm("mov.b64 %0, {%1, %1};" : "=l"(r) : "f"(x));
    return r;
}
__device__ __forceinline__ void fma2(unsigned long long& d,
                                     unsigned long long a,
                                     unsigned long long b) {
    asm("fma.rn.f32x2 %0, %1, %2, %0;" : "+l"(d) : "l"(a), "l"(b));
}
__device__ __forceinline__ float2 up2(unsigned long long v) {
    float lo, hi;
    asm("mov.b64 {%0, %1}, %2;" : "=f"(lo), "=f"(hi) : "l"(v));
    return make_float2(lo, hi);
}
__device__ __forceinline__ void cp16(unsigned int dst, const void* src, int bytes) {
    asm volatile("cp.async.cg.shared.global [%0], [%1], 16, %2;\n"
                 :: "r"(dst), "l"(src), "r"(bytes));
}
__device__ __forceinline__ void cp_commit() {
    asm volatile("cp.async.commit_group;\n");
}
__device__ __forceinline__ void cp_wait0() {
    asm volatile("cp.async.wait_group 0;\n");
}

// ---------------------------------------------------------------------------
// Fused gate+up GEMM. R15 core (proven 10.2ms, fma=74.8%) with cp.async
// loaders replacing register staging: fewer issue slots competing with fma2,
// ~35 staging regs freed. Smem layout [k][row] as before; loader writes
// 4 consecutive floats of column ar at rows ac..ac+3 -> 4 separate STS before,
// now must keep [k][row] layout, so cp.async writes a float4 along k? NO:
// cp.async copies 16 contiguous bytes; in [k][row] layout the 4 k-values of
// one row are NOT contiguous. Switch tile layout to [row][k] (row-major,
// stride 20) and swap indexing in compute: a-pairs along rows now need
// [row][k] gather; instead keep B in [row][k] and A transposed at compute?
// Resolution: store tiles ROW-major [128][20]; compute reads
//   A: per thread 16 rows at column kk -> 16 scalar LDS (was 4x LDS.128)
//   B: 8 cols at kk -> 8 scalar LDS
// That TRIPLES lds count. Instead keep layout [k][row] for COMPUTE efficiency
// and have cp.async target A^T staging impossible...
// Chosen: tiles stored [row][kstride=20] (cp.async-friendly); compute loops
// restructured: load per-kk A-column via 8x LDS.64 pairs (rows contiguous? no)
// -> Final decision: keep [k][row] compute layout for B only; A uses
// [row][k] with per-thread row-pair packing done at REGISTER level:
// each thread reads its 8 row-pairs as 8 x LDS.64 from [row][k]? rows of a
// pair are adjacent rows -> different smem rows, not contiguous.
// => Simplest correct scheme that keeps LDS.128: store tiles TRANSPOSED by
// cp.async destination: A kept [k][row] but cp.async copies from GLOBAL
// where 4 k-values are contiguous; dest [k][row] needs them strided. Can't.
// => Use [row][k] for both tiles and change compute to column-broadcast form:
//    per kk: B column values b[8] via 8 scalar LDS (bank-conflict-free,
//    stride 20), A row values: thread's 16 rows at kk: 16 scalar LDS.
// LDS count/iter/thread: 16*(16+8)=384 scalar LDS vs prior 96 vector LDS...
// worse. ABANDON layout change: keep R15 LDG+STS loaders for A (transpose
// needed) and use cp.async ONLY for B tiles? B also needs [k][row].
// CONCLUSION: cp.async incompatible with transposed smem layout; instead
// reduce loader cost by having A-tile stored [row][k] ONLY for staging and
// doing the transpose... too complex. This kernel keeps R15 loaders but
// moves the STS of the next tile BEFORE the compute loop (stores overlap
// fma instead of bursting right before the barrier).
// ---------------------------------------------------------------------------
template <int GATHER>
__global__ void __launch_bounds__(128, 2)
k_gateup(const float* __restrict__ X,
         const float* __restrict__ Wgb,
         const float* __restrict__ Wub,
         int N, int Kd) {
    int rows, base;
    const float* Wg;
    const float* Wu;
    if (GATHER) {
        int e = blockIdx.z;
        rows = g_cnt[e];
        base = g_off[e];
        size_t wo = (size_t)e * N * Kd;
        Wg = Wgb + wo; Wu = Wub + wo;
    } else {
        rows = T_TOK; base = 0; Wg = Wgb; Wu = Wub;
    }
    int rowBase = blockIdx.y * 128;
    if (rowBase >= rows) return;
    int colBase = blockIdx.x * 64;

    __shared__ float As[2][16][132];
    __shared__ float Bs[2][16][132];

    const int tid = threadIdx.x;
    const int tx = tid & 15;
    const int ty = tid >> 4;

    int ar[4], ac[4];
    const float* aptr[4];
    bool aval[4];
    const float* bptr[4];
    int br[4], bc[4];
#pragma unroll
    for (int i = 0; i < 4; i++) {
        int idx = tid + i * 128;
        ar[i] = idx >> 2;
        ac[i] = (idx & 3) * 4;
        int grow = rowBase + ar[i];
        aval[i] = grow < rows;
        if (GATHER) {
            int tok = aval[i] ? g_rowtok[base + grow] : 0;
            aptr[i] = X + (size_t)tok * Kd + ac[i];
        } else {
            aptr[i] = X + (size_t)(aval[i] ? grow : 0) * Kd + ac[i];
        }
        br[i] = idx >> 2;
        bc[i] = (idx & 3) * 4;
        if (br[i] < 64)
            bptr[i] = Wg + (size_t)(colBase + br[i]) * Kd + bc[i];
        else
            bptr[i] = Wu + (size_t)(colBase + br[i] - 64) * Kd + bc[i];
    }

    unsigned long long accg2[8][4];
    unsigned long long accu2[8][4];
#pragma unroll
    for (int p = 0; p < 8; p++)
#pragma unroll
        for (int j = 0; j < 4; j++) { accg2[p][j] = 0ULL; accu2[p][j] = 0ULL; }

    const int KT = Kd >> 4;

    float4 sva[4], svb[4];
#pragma unroll
    for (int i = 0; i < 4; i++) {
        sva[i] = aval[i] ? *reinterpret_cast<const float4*>(aptr[i])
                         : make_float4(0.f, 0.f, 0.f, 0.f);
        svb[i] = *reinterpret_cast<const float4*>(bptr[i]);
    }
#pragma unroll
    for (int i = 0; i < 4; i++) {
        As[0][ac[i] + 0][ar[i]] = sva[i].x;
        As[0][ac[i] + 1][ar[i]] = sva[i].y;
        As[0][ac[i] + 2][ar[i]] = sva[i].z;
        As[0][ac[i] + 3][ar[i]] = sva[i].w;
        Bs[0][bc[i] + 0][br[i]] = svb[i].x;
        Bs[0][bc[i] + 1][br[i]] = svb[i].y;
        Bs[0][bc[i] + 2][br[i]] = svb[i].z;
        Bs[0][bc[i] + 3][br[i]] = svb[i].w;
    }
    // preload stage-1 globals into registers before entering loop
#pragma unroll
    for (int i = 0; i < 4; i++) {
        sva[i] = aval[i] ? *reinterpret_cast<const float4*>(aptr[i] + 16)
                         : make_float4(0.f, 0.f, 0.f, 0.f);
        svb[i] = *reinterpret_cast<const float4*>(bptr[i] + 16);
    }
    __syncthreads();

    for (int kt = 0; kt < KT; kt++) {
        int cur = kt & 1;
        int nxt = cur ^ 1;
        // store staged next tile FIRST (overlaps with fma of current tile,
        // instead of bursting right before the barrier)
        if (kt + 1 < KT) {
#pragma unroll
            for (int i = 0; i < 4; i++) {
                As[nxt][ac[i] + 0][ar[i]] = sva[i].x;
                As[nxt][ac[i] + 1][ar[i]] = sva[i].y;
                As[nxt][ac[i] + 2][ar[i]] = sva[i].z;
                As[nxt][ac[i] + 3][ar[i]] = sva[i].w;
                Bs[nxt][bc[i] + 0][br[i]] = svb[i].x;
                Bs[nxt][bc[i] + 1][br[i]] = svb[i].y;
                Bs[nxt][bc[i] + 2][br[i]] = svb[i].z;
                Bs[nxt][bc[i] + 3][br[i]] = svb[i].w;
            }
        }
        // issue loads for tile kt+2 (in flight under the whole compute loop)
        if (kt + 2 < KT) {
            int k0 = (kt + 2) << 4;
#pragma unroll
            for (int i = 0; i < 4; i++) {
                sva[i] = aval[i] ? *reinterpret_cast<const float4*>(aptr[i] + k0)
                                 : make_float4(0.f, 0.f, 0.f, 0.f);
                svb[i] = *reinterpret_cast<const float4*>(bptr[i] + k0);
            }
        }
#pragma unroll
        for (int kk = 0; kk < 16; kk++) {
            const ulonglong2* ap =
                reinterpret_cast<const ulonglong2*>(&As[cur][kk][ty * 16]);
            ulonglong2 av0 = ap[0], av1 = ap[1], av2 = ap[2], av3 = ap[3];
            unsigned long long a2[8] = {av0.x, av0.y, av1.x, av1.y,
                                        av2.x, av2.y, av3.x, av3.y};
            float4 bg = *reinterpret_cast<const float4*>(&Bs[cur][kk][tx * 4]);
            float4 bu = *reinterpret_cast<const float4*>(&Bs[cur][kk][64 + tx * 4]);
            unsigned long long bg2[4] = {pk2(bg.x), pk2(bg.y), pk2(bg.z), pk2(bg.w)};
            unsigned long long bu2[4] = {pk2(bu.x), pk2(bu.y), pk2(bu.z), pk2(bu.w)};
#pragma unroll
            for (int p = 0; p < 8; p++) {
#pragma unroll
                for (int j = 0; j < 4; j++) {
                    fma2(accg2[p][j], a2[p], bg2[j]);
                    fma2(accu2[p][j], a2[p], bu2[j]);
                }
            }
        }
        __syncthreads();
    }

#pragma unroll
    for (int p = 0; p < 8; p++) {
        float2 g2[4], u2[4];
#pragma unroll
        for (int j = 0; j < 4; j++) { g2[j] = up2(accg2[p][j]); u2[j] = up2(accu2[p][j]); }
        int growL = rowBase + ty * 16 + 2 * p;
        if (growL < rows) {
            float4 hv;
            hv.x = (g2[0].x / (1.f + expf(-g2[0].x))) * u2[0].x;
            hv.y = (g2[1].x / (1.f + expf(-g2[1].x))) * u2[1].x;
            hv.z = (g2[2].x / (1.f + expf(-g2[2].x))) * u2[2].x;
            hv.w = (g2[3].x / (1.f + expf(-g2[3].x))) * u2[3].x;
            *reinterpret_cast<float4*>(
                &g_hdn[(size_t)(base + growL) * N + colBase + tx * 4]) = hv;
        }
        int growH = growL + 1;
        if (growH < rows) {
            float4 hv;
            hv.x = (g2[0].y / (1.f + expf(-g2[0].y))) * u2[0].y;
            hv.y = (g2[1].y / (1.f + expf(-g2[1].y))) * u2[1].y;
            hv.z = (g2[2].y / (1.f + expf(-g2[2].y))) * u2[2].y;
            hv.w = (g2[3].y / (1.f + expf(-g2[3].y))) * u2[3].y;
            *reinterpret_cast<float4*>(
                &g_hdn[(size_t)(base + growH) * N + colBase + tx * 4]) = hv;
        }
    }
}

// ---------------------------------------------------------------------------
// Down GEMM (same store-early / load-two-ahead pipeline)
// ---------------------------------------------------------------------------
template <int GATHER>
__global__ void __launch_bounds__(128, 2)
k_down(const float* __restrict__ Wdb,
       float* __restrict__ Out,
       int N, int Kd) {
    int rows, base;
    const float* Wd;
    if (GATHER) {
        int e = blockIdx.z;
        rows = g_cnt[e];
        base = g_off[e];
        Wd = Wdb + (size_t)e * N * Kd;
    } else {
        rows = T_TOK; base = 0; Wd = Wdb;
    }
    int rowBase = blockIdx.y * 128;
    if (rowBase >= rows) return;
    int colBase = blockIdx.x * 128;

    __shared__ float As[2][16][132];
    __shared__ float Bs[2][16][132];

    const int tid = threadIdx.x;
    const int tx = tid & 15;
    const int ty = tid >> 4;

    int ar[4], ac[4];
    const float* aptr[4];
    bool aval[4];
    const float* bptr[4];
    int br[4], bc[4];
#pragma unroll
    for (int i = 0; i < 4; i++) {
        int idx = tid + i * 128;
        ar[i] = idx >> 2;
        ac[i] = (idx & 3) * 4;
        int grow = rowBase + ar[i];
        aval[i] = grow < rows;
        aptr[i] = g_hdn + (size_t)(base + (aval[i] ? grow : 0)) * Kd + ac[i];
        br[i] = idx >> 2;
        bc[i] = (idx & 3) * 4;
        bptr[i] = Wd + (size_t)(colBase + br[i]) * Kd + bc[i];
    }

    unsigned long long acc2[8][8];
#pragma unroll
    for (int p = 0; p < 8; p++)
#pragma unroll
        for (int j = 0; j < 8; j++) acc2[p][j] = 0ULL;

    const int KT = Kd >> 4;

    float4 sva[4], svb[4];
#pragma unroll
    for (int i = 0; i < 4; i++) {
        sva[i] = aval[i] ? *reinterpret_cast<const float4*>(aptr[i])
                         : make_float4(0.f, 0.f, 0.f, 0.f);
        svb[i] = *reinterpret_cast<const float4*>(bptr[i]);
    }
#pragma unroll
    for (int i = 0; i < 4; i++) {
        As[0][ac[i] + 0][ar[i]] = sva[i].x;
        As[0][ac[i] + 1][ar[i]] = sva[i].y;
        As[0][ac[i] + 2][ar[i]] = sva[i].z;
        As[0][ac[i] + 3][ar[i]] = sva[i].w;
        Bs[0][bc[i] + 0][br[i]] = svb[i].x;
        Bs[0][bc[i] + 1][br[i]] = svb[i].y;
        Bs[0][bc[i] + 2][br[i]] = svb[i].z;
        Bs[0][bc[i] + 3][br[i]] = svb[i].w;
    }
#pragma unroll
    for (int i = 0; i < 4; i++) {
        sva[i] = aval[i] ? *reinterpret_cast<const float4*>(aptr[i] + 16)
                         : make_float4(0.f, 0.f, 0.f, 0.f);
        svb[i] = *reinterpret_cast<const float4*>(bptr[i] + 16);
    }
    __syncthreads();

    for (int kt = 0; kt < KT; kt++) {
        int cur = kt & 1;
        int nxt = cur ^ 1;
        if (kt + 1 < KT) {
#pragma unroll
            for (int i = 0; i < 4; i++) {
                As[nxt][ac[i] + 0][ar[i]] = sva[i].x;
                As[nxt][ac[i] + 1][ar[i]] = sva[i].y;
                As[nxt][ac[i] + 2][ar[i]] = sva[i].z;
                As[nxt][ac[i] + 3][ar[i]] = sva[i].w;
                Bs[nxt][bc[i] + 0][br[i]] = svb[i].x;
                Bs[nxt][bc[i] + 1][br[i]] = svb[i].y;
                Bs[nxt][bc[i] + 2][br[i]] = svb[i].z;
                Bs[nxt][bc[i] + 3][br[i]] = svb[i].w;
            }
        }
        if (kt + 2 < KT) {
            int k0 = (kt + 2) << 4;
#pragma unroll
            for (int i = 0; i < 4; i++) {
                sva[i] = aval[i] ? *reinterpret_cast<const float4*>(aptr[i] + k0)
                                 : make_float4(0.f, 0.f, 0.f, 0.f);
                svb[i] = *reinterpret_cast<const float4*>(bptr[i] + k0);
            }
        }
#pragma unroll
        for (int kk = 0; kk < 16; kk++) {
            const ulonglong2* ap =
                reinterpret_cast<const ulonglong2*>(&As[cur][kk][ty * 16]);
            ulonglong2 av0 = ap[0], av1 = ap[1], av2 = ap[2], av3 = ap[3];
            unsigned long long a2[8] = {av0.x, av0.y, av1.x, av1.y,
                                        av2.x, av2.y, av3.x, av3.y};
            float4 b0 = *reinterpret_cast<const float4*>(&Bs[cur][kk][tx * 4]);
            float4 b1 = *reinterpret_cast<const float4*>(&Bs[cur][kk][64 + tx * 4]);
            unsigned long long b2[8] = {pk2(b0.x), pk2(b0.y), pk2(b0.z), pk2(b0.w),
                                        pk2(b1.x), pk2(b1.y), pk2(b1.z), pk2(b1.w)};
#pragma unroll
            for (int p = 0; p < 8; p++)
#pragma unroll
                for (int j = 0; j < 8; j++)
                    fma2(acc2[p][j], a2[p], b2[j]);
        }
        __syncthreads();
    }

#pragma unroll
    for (int p = 0; p < 8; p++) {
        float2 c2[8];
#pragma unroll
        for (int j = 0; j < 8; j++) c2[j] = up2(acc2[p][j]);
#pragma unroll
        for (int half = 0; half < 2; half++) {
            int grow = rowBase + ty * 16 + 2 * p + half;
            if (grow >= rows) continue;
            if (GATHER) {
                int tok = g_rowtok[base + grow];
                float w = g_roww[base + grow];
                float* op0 = Out + (size_t)tok * N + colBase + tx * 4;
                float* op1 = op0 + 64;
#pragma unroll
                for (int j = 0; j < 4; j++) {
                    float v0 = half ? c2[j].y : c2[j].x;
                    float v1 = half ? c2[j + 4].y : c2[j + 4].x;
                    atomicAdd(op0 + j, w * v0);
                    atomicAdd(op1 + j, w * v1);
                }
            } else {
                float w = g_sgate[grow];
                float* op0 = Out + (size_t)grow * N + colBase + tx * 4;
                float4 s0, s1;
                s0.x = w * (half ? c2[0].y : c2[0].x);
                s0.y = w * (half ? c2[1].y : c2[1].x);
                s0.z = w * (half ? c2[2].y : c2[2].x);
                s0.w = w * (half ? c2[3].y : c2[3].x);
                s1.x = w * (half ? c2[4].y : c2[4].x);
                s1.y = w * (half ? c2[5].y : c2[5].x);
                s1.z = w * (half ? c2[6].y : c2[6].x);
                s1.w = w * (half ? c2[7].y : c2[7].x);
                *reinterpret_cast<float4*>(op0) = s0;
                *reinterpret_cast<float4*>(op0 + 64) = s1;
            }
        }
    }
}

// ---------------------------------------------------------------------------
extern "C" void kernel_launch(void* const* d_in, const int* in_sizes, int n_in,
                              void* d_out, int out_size) {
    const float* x    = (const float*)d_in[0];  // [B,S,H]
    const float* gw   = (const float*)d_in[1];  // [E,H]
    const float* egw  = (const float*)d_in[2];  // [E,FE,H]
    const float* euw  = (const float*)d_in[3];  // [E,FE,H]
    const float* edw  = (const float*)d_in[4];  // [E,H,FE]
    const float* sgw  = (const float*)d_in[5];  // [FS,H]
    const float* suw  = (const float*)d_in[6];  // [FS,H]
    const float* sdw  = (const float*)d_in[7];  // [H,FS]
    const float* segw = (const float*)d_in[8];  // [1,H]
    float* out = (float*)d_out;

    k_router<<<T_TOK / 8, 256>>>(x, gw, segw);       // 1
    k_offsets<<<1, 256>>>();                          // 2
    k_assign<<<T_TOK / 256, 256>>>();                 // 3

    // 4th launch = profiled GEMM. Shared path first; its down kernel
    // initializes out with plain weighted stores (no memset).
    k_gateup<0><<<dim3(FS / 64, T_TOK / 128, 1), 128>>>(x, sgw, suw, FS, HDIM);
    k_down<0><<<dim3(HDIM / 128, T_TOK / 128, 1), 128>>>(sdw, out, HDIM, FS);

    // Expert path: fused gate+up (gathered), then down + weighted atomic add
    k_gateup<1><<<dim3(FE / 64, T_TOK / 128, NEXP), 128>>>(x, egw, euw, FE, HDIM);
    k_down<1><<<dim3(HDIM / 128, T_TOK / 128, NEXP), 128>>>(edw, out, HDIM, FE);
}